// round 16
// baseline (speedup 1.0000x reference)
#include <cuda_runtime.h>
#include <cuda_bf16.h>
#include <math.h>
#include <stdint.h>

#define BATCH 16
#define CIN   512
#define FH    50
#define FW    50
#define HW    2500
#define NANCH 9
#define NTOT  (HW*NANCH)
#define PRE   512
#define POST  128
#define IMGW  800.0f
#define IMGH  800.0f
#define OCB   128
#define PXB   128
#define NPXT  20
#define XROWS 2688
#define XPAD  64
#define RS2   40                  // padded stride (bf16) -> 80B, 16B-aligned
#define TILE2 (128*RS2*2)         // 10240 B per split tile
#define BUF2  (6*TILE2)           // 61440 B per stage buffer
#define NCH   144                 // half-chunks (32 ic each)

#define KAHAN_ADD(s, c, p) do {                        \
    float _y = __fsub_rn((p), (c));                    \
    float _t = __fadd_rn((s), _y);                     \
    (c) = __fsub_rn(__fsub_rn(_t, (s)), _y);           \
    (s) = _t;                                          \
} while (0)

__device__ float g_shared[(size_t)BATCH*CIN*HW];
__device__ float g_scores[(size_t)BATCH*NTOT];
__device__ int   g_topidx[BATCH*PRE];
__device__ float g_topscore[BATCH*PRE];
__device__ __align__(16) __nv_bfloat16 g_xsT[9][BATCH][XROWS][CIN];
__device__ __align__(16) __nv_bfloat16 g_wA[(size_t)864*8192];

__device__ __forceinline__ uint32_t smem_u32(const void* p) {
    uint32_t a;
    asm("{ .reg .u64 t; cvta.to.shared.u64 t, %1; cvt.u32.u64 %0, t; }"
        : "=r"(a) : "l"(p));
    return a;
}
__device__ __forceinline__ void split3(float v, __nv_bfloat16& s0,
                                       __nv_bfloat16& s1, __nv_bfloat16& s2) {
    s0 = __float2bfloat16_rn(v);
    float r1 = __fsub_rn(v, __bfloat162float(s0));
    s1 = __float2bfloat16_rn(r1);
    float r2 = __fsub_rn(r1, __bfloat162float(s1));
    s2 = __float2bfloat16_rn(r2);
}

__global__ __launch_bounds__(256) void zero_pads_kernel() {
    const int nrows = XPAD + (XROWS - XPAD - HW);
    size_t total = (size_t)9 * BATCH * nrows * CIN / 8;
    uint4 z = make_uint4(0,0,0,0);
    for (size_t i = blockIdx.x * 256ull + threadIdx.x; i < total;
         i += (size_t)gridDim.x * 256ull) {
        size_t e = i * 8;
        int ic  = e % CIN;
        size_t r = e / CIN;
        int row = r % nrows;
        size_t jb = r / nrows;
        int b = jb % BATCH;
        int j = jb / BATCH;
        int xrow = (row < XPAD) ? row : (row - XPAD + XPAD + HW);
        *(uint4*)&g_xsT[j][b][xrow][ic] = z;
    }
}

__global__ __launch_bounds__(256) void prep_x_kernel(const float* __restrict__ x) {
    __shared__ float Xt[32][34];
    const int p0x = blockIdx.x * 32;
    const int i0  = blockIdx.y * 32;
    const int b   = blockIdx.z;
    const int tid = threadIdx.x;
    for (int e = tid; e < 32*34; e += 256) {
        int ic = e / 34, c = e % 34;
        int p = p0x - 1 + c;
        Xt[ic][c] = (p >= 0 && p < HW)
            ? x[((size_t)b*CIN + i0 + ic)*HW + p] : 0.f;
    }
    __syncthreads();
    for (int e = tid; e < 32*32; e += 256) {
        int pl = e >> 5, ic = e & 31;
        int p = p0x + pl;
        if (p >= HW) continue;
        int xcol = p % FW;
#pragma unroll
        for (int dxi = 0; dxi < 3; dxi++) {
            int xc = xcol + dxi - 1;
            float v = (xc >= 0 && xc < FW) ? Xt[ic][pl + dxi] : 0.f;
            __nv_bfloat16 s0, s1, s2;
            split3(v, s0, s1, s2);
            g_xsT[0*3 + dxi][b][p + XPAD][i0 + ic] = s0;
            g_xsT[1*3 + dxi][b][p + XPAD][i0 + ic] = s1;
            g_xsT[2*3 + dxi][b][p + XPAD][i0 + ic] = s2;
        }
    }
}

__global__ __launch_bounds__(256) void prep_w_kernel(const float* __restrict__ w1) {
    const int id = blockIdx.x;
    const int ocblk = id & 3;
    const int icblk = (id >> 2) & 7;
    const int tmp = id >> 5;
    const int t = tmp % 9;
    const int j = tmp / 9;
    __nv_bfloat16* dst = g_wA + (size_t)id * 8192;
    for (int e = threadIdx.x; e < 8192; e += 256) {
        int r = e >> 6, c = e & 63;
        int oc = ocblk*128 + r;
        int ic = icblk*64 + c;
        float w = w1[(size_t)oc*(CIN*9) + ic*9 + t];
        __nv_bfloat16 s0, s1, s2;
        split3(w, s0, s1, s2);
        dst[r*64 + c] = (j == 0) ? s0 : (j == 1) ? s1 : s2;
    }
}

// stage one 32-ic half-chunk: A 3 tiles + B 3 tiles, 128 rows x 32 ic
__device__ __forceinline__ void stage_chunk_async(
    uint32_t buf, int ch, int ocblk, int b, int p0, int tid)
{
    const int t = ch >> 4, sub = ch & 15;
    const int dy = t / 3 - 1, dxi = t % 3;
    const int icblk64 = sub >> 1, half = sub & 1;
    for (int e = tid; e < 1536; e += 256) {
        int j = e / 512, r = (e >> 2) & 127, c4 = e & 3;
        const __nv_bfloat16* src = g_wA +
            (size_t)(((j*9 + t)*8 + icblk64)*4 + ocblk) * 8192
            + r*64 + half*32 + c4*8;
        uint32_t d = buf + (uint32_t)(j*TILE2 + r*(RS2*2) + c4*16);
        asm volatile("cp.async.cg.shared.global [%0], [%1], 16;"
                     :: "r"(d), "l"(src));
    }
    const int rowbase = p0 + dy*FW + XPAD;
    for (int e = tid; e < 1536; e += 256) {
        int j = e / 512, r = (e >> 2) & 127, c4 = e & 3;
        const __nv_bfloat16* src =
            &g_xsT[j*3 + dxi][b][rowbase + r][sub*32] + c4*8;
        uint32_t d = buf + (uint32_t)(3*TILE2 + j*TILE2 + r*(RS2*2) + c4*16);
        asm volatile("cp.async.cg.shared.global [%0], [%1], 16;"
                     :: "r"(d), "l"(src));
    }
    asm volatile("cp.async.commit_group;");
}

__global__ __launch_bounds__(256, 1)
void conv_mma_kernel(const float* __restrict__ b1) {
    extern __shared__ unsigned char dsm[];
    const uint32_t sb0 = (smem_u32(dsm) + 15u) & ~15u;

    const int tid  = threadIdx.x;
    const int wid  = tid >> 5;
    const int lane = tid & 31;
    const int pxblk = blockIdx.x, ocblk = blockIdx.y, b = blockIdx.z;
    const int p0 = pxblk * PXB;
    const int warp_m0 = (wid & 1) * 64;
    const int warp_n0 = (wid >> 1) * 32;

    float accL[4][4][4], accS[4][4][4];
#pragma unroll
    for (int mt = 0; mt < 4; mt++)
#pragma unroll
        for (int nt = 0; nt < 4; nt++)
#pragma unroll
            for (int r = 0; r < 4; r++) { accL[mt][nt][r] = 0.f; accS[mt][nt][r] = 0.f; }

    stage_chunk_async(sb0 + 0*BUF2, 0, ocblk, b, p0, tid);
    stage_chunk_async(sb0 + 1*BUF2, 1, ocblk, b, p0, tid);

    int cur_i = 0;                     // ch % 3
    for (int ch = 0; ch < NCH; ch++) {
        const uint32_t cur = sb0 + (uint32_t)(cur_i * BUF2);

        if (ch < NCH - 2)
            asm volatile("cp.async.wait_group 1;" ::: "memory");
        else
            asm volatile("cp.async.wait_group 0;" ::: "memory");
        __syncthreads();

        if (ch + 2 < NCH) {
            int nxt_i = cur_i + 2; if (nxt_i >= 3) nxt_i -= 3;
            stage_chunk_async(sb0 + (uint32_t)(nxt_i * BUF2),
                              ch + 2, ocblk, b, p0, tid);
        }

        const uint32_t sbA = cur;
        const uint32_t sbB = cur + 3*TILE2;

#pragma unroll
        for (int ks = 0; ks < 2; ks++) {
            const int k0 = ks * 16;
            uint32_t bf[3][4][2];
#pragma unroll
            for (int s = 0; s < 3; s++)
#pragma unroll
                for (int nt = 0; nt < 4; nt++) {
                    int row = warp_n0 + nt*8 + (lane & 7);
                    int colb = (k0 + ((lane >> 3) & 1)*8) * 2;
                    uint32_t a = sbB + s*TILE2 + row*(RS2*2) + colb;
                    asm volatile(
                        "ldmatrix.sync.aligned.m8n8.x2.shared.b16 {%0,%1}, [%2];"
                        : "=r"(bf[s][nt][0]), "=r"(bf[s][nt][1]) : "r"(a));
                }
#pragma unroll
            for (int j = 0; j < 3; j++) {
                uint32_t af[4][4];
#pragma unroll
                for (int mt = 0; mt < 4; mt++) {
                    int row = warp_m0 + mt*16 + (lane & 15);
                    int colb = (k0 + (lane >> 4)*8) * 2;
                    uint32_t a = sbA + j*TILE2 + row*(RS2*2) + colb;
                    asm volatile(
                        "ldmatrix.sync.aligned.m8n8.x4.shared.b16 {%0,%1,%2,%3}, [%4];"
                        : "=r"(af[mt][0]), "=r"(af[mt][1]),
                          "=r"(af[mt][2]), "=r"(af[mt][3]) : "r"(a));
                }
                const int nk = (j == 0) ? 3 : (j == 1) ? 2 : 1;
#pragma unroll
                for (int k = 0; k < 3; k++) {
                    if (k >= nk) break;
#pragma unroll
                    for (int mt = 0; mt < 4; mt++)
#pragma unroll
                        for (int nt = 0; nt < 4; nt++) {
                            asm volatile(
                                "mma.sync.aligned.m16n8k16.row.col.f32.bf16.bf16.f32 "
                                "{%0,%1,%2,%3}, {%4,%5,%6,%7}, {%8,%9}, {%0,%1,%2,%3};"
                                : "+f"(accS[mt][nt][0]), "+f"(accS[mt][nt][1]),
                                  "+f"(accS[mt][nt][2]), "+f"(accS[mt][nt][3])
                                : "r"(af[mt][0]), "r"(af[mt][1]),
                                  "r"(af[mt][2]), "r"(af[mt][3]),
                                  "r"(bf[k][nt][0]), "r"(bf[k][nt][1]));
                        }
                }
            }
        }
        if ((ch & 7) == 7) {
#pragma unroll
            for (int mt = 0; mt < 4; mt++)
#pragma unroll
                for (int nt = 0; nt < 4; nt++)
#pragma unroll
                    for (int r = 0; r < 4; r++) {
                        accL[mt][nt][r] = __fadd_rn(accL[mt][nt][r],
                                                    accS[mt][nt][r]);
                        accS[mt][nt][r] = 0.f;
                    }
        }
        cur_i++; if (cur_i >= 3) cur_i = 0;
    }

#pragma unroll
    for (int mt = 0; mt < 4; mt++) {
#pragma unroll
        for (int half = 0; half < 2; half++) {
            int oc = ocblk*128 + warp_m0 + mt*16 + (lane >> 2) + half*8;
            float bias = b1[oc];
            float* op = g_shared + ((size_t)b*CIN + oc)*HW;
#pragma unroll
            for (int nt = 0; nt < 4; nt++) {
#pragma unroll
                for (int e = 0; e < 2; e++) {
                    int px = p0 + warp_n0 + nt*8 + (lane & 3)*2 + e;
                    if (px < HW) {
                        float v = __fadd_rn(accL[mt][nt][half*2 + e], bias);
                        op[px] = fmaxf(v, 0.f);
                    }
                }
            }
        }
    }
}

__global__ __launch_bounds__(256) void cls_kernel(
    const float* __restrict__ w2, const float* __restrict__ b2)
{
    __shared__ float w2s[9][512];
    const int b = blockIdx.y;
    const int p = blockIdx.x * 256 + threadIdx.x;
    for (int i = threadIdx.x; i < 9*512; i += 256)
        w2s[i/512][i%512] = w2[i];
    __syncthreads();
    if (p >= HW) return;
    float acc[9], cmp[9];
#pragma unroll
    for (int a = 0; a < 9; a++) { acc[a] = 0.f; cmp[a] = 0.f; }
    const float* sp = g_shared + (size_t)b * CIN * HW + p;
    for (int c = 0; c < CIN; c++) {
        float v = sp[(size_t)c * HW];
#pragma unroll
        for (int a = 0; a < 9; a++)
            KAHAN_ADD(acc[a], cmp[a], __fmul_rn(v, w2s[a][c]));
    }
    float* outp = g_scores + (size_t)b * NTOT + (size_t)p * 9;
#pragma unroll
    for (int a = 0; a < 9; a++) {
        float logit = __fadd_rn(__fsub_rn(acc[a], cmp[a]), b2[a]);
        double sg = 1.0 / (1.0 + exp(-(double)logit));
        outp[a] = (float)sg;
    }
}

__global__ __launch_bounds__(1024) void topk_kernel()
{
    extern __shared__ unsigned char smraw[];
    unsigned int* hist = (unsigned int*)smraw;
    unsigned int* csum = hist + 32768;
    unsigned long long* cand = (unsigned long long*)(csum + 1024);
    __shared__ int s_tb, s_cntgt, s_thr, s_cnt;
    const int b = blockIdx.x, tid = threadIdx.x;
    const float* sc = g_scores + (size_t)b * NTOT;

    for (int i = tid; i < 32768; i += 1024) hist[i] = 0;
    __syncthreads();
    for (int i = tid; i < NTOT; i += 1024)
        atomicAdd(&hist[__float_as_uint(sc[i]) >> 15], 1u);
    __syncthreads();
    { unsigned int cs = 0;
#pragma unroll 4
      for (int k = 0; k < 32; k++) cs += hist[tid*32 + k];
      csum[tid] = cs; }
    __syncthreads();
    if (tid == 0) {
        unsigned int accum = 0;
        int ch = 1023;
        for (; ch > 0; ch--) { if (accum + csum[ch] >= PRE) break; accum += csum[ch]; }
        int bk = ch*32 + 31;
        for (; bk > ch*32; bk--) { if (accum + hist[bk] >= PRE) break; accum += hist[bk]; }
        s_tb = bk; s_cntgt = (int)accum;
    }
    __syncthreads();
    const int tb = s_tb, cntgt = s_cntgt;

    for (int i = tid; i < 32768; i += 1024) hist[i] = 0;
    __syncthreads();
    for (int i = tid; i < NTOT; i += 1024) {
        unsigned int bits = __float_as_uint(sc[i]);
        if ((int)(bits >> 15) == tb) atomicAdd(&hist[bits & 0x7FFF], 1u);
    }
    __syncthreads();
    { unsigned int cs = 0;
#pragma unroll 4
      for (int k = 0; k < 32; k++) cs += hist[tid*32 + k];
      csum[tid] = cs; }
    __syncthreads();
    if (tid == 0) {
        unsigned int accum = (unsigned int)cntgt;
        int ch = 1023;
        for (; ch > 0; ch--) { if (accum + csum[ch] >= PRE) break; accum += csum[ch]; }
        int bk = ch*32 + 31;
        for (; bk > ch*32; bk--) { if (accum + hist[bk] >= PRE) break; accum += hist[bk]; }
        s_thr = (tb << 15) | bk;
        s_cnt = 0;
    }
    __syncthreads();
    const unsigned int thrbits = (unsigned int)s_thr;

    for (int i = tid; i < NTOT; i += 1024) {
        unsigned int bits = __float_as_uint(sc[i]);
        if (bits >= thrbits) {
            int pos = atomicAdd(&s_cnt, 1);
            if (pos < 1024)
                cand[pos] = ((unsigned long long)bits << 32) |
                            (unsigned long long)(0xFFFFFFFFu - (unsigned int)i);
        }
    }
    __syncthreads();
    int cnt = s_cnt; if (cnt > 1024) cnt = 1024;
    if (tid >= cnt) cand[tid] = 0ULL;
    __syncthreads();

    for (int k = 2; k <= 1024; k <<= 1) {
        for (int j = k >> 1; j > 0; j >>= 1) {
            int ixj = tid ^ j;
            if (ixj > tid) {
                unsigned long long a = cand[tid], c = cand[ixj];
                bool up = ((tid & k) == 0);
                if (up ? (a < c) : (a > c)) { cand[tid] = c; cand[ixj] = a; }
            }
            __syncthreads();
        }
    }
    if (tid < PRE) {
        unsigned long long key = cand[tid];
        unsigned int idx = 0xFFFFFFFFu - (unsigned int)(key & 0xFFFFFFFFull);
        g_topidx[b*PRE + tid]   = (int)idx;
        g_topscore[b*PRE + tid] = __uint_as_float((unsigned int)(key >> 32));
    }
}

#define W3S_FLOATS (36*513)
__global__ __launch_bounds__(512) void proposal_kernel(
    const float* __restrict__ w3, const float* __restrict__ b3,
    float* __restrict__ out)
{
    extern __shared__ float sm[];
    float*  w3s   = sm;
    float4* boxes = (float4*)(sm + W3S_FLOATS);
    float*  ss    = (float*)(boxes + PRE);
    int*    keep  = (int*)(ss + PRE);
    __shared__ uint32_t aliveW[16];
    __shared__ int warpcnt[16];
    const int b = blockIdx.x;
    const int j = threadIdx.x;
    const int lane = j & 31, warp = j >> 5;

    for (int i = j; i < 36*512; i += 512) {
        int row = i >> 9, c = i & 511;
        w3s[row*513 + c] = w3[i];
    }
    __syncthreads();

    const int   idx = g_topidx[b*PRE + j];
    const float s   = g_topscore[b*PRE + j];
    const int p = idx / 9, a = idx % 9;

    float so[4] = {0.f,0.f,0.f,0.f}, co[4] = {0.f,0.f,0.f,0.f};
    {
        const float* col = g_shared + (size_t)b * CIN * HW + p;
        const float* w0 = w3s + (a*4+0)*513;
        const float* w1r= w3s + (a*4+1)*513;
        const float* w2r= w3s + (a*4+2)*513;
        const float* w3r= w3s + (a*4+3)*513;
        for (int c = 0; c < CIN; c++) {
            float v = col[(size_t)c * HW];
            KAHAN_ADD(so[0], co[0], __fmul_rn(v, w0[c]));
            KAHAN_ADD(so[1], co[1], __fmul_rn(v, w1r[c]));
            KAHAN_ADD(so[2], co[2], __fmul_rn(v, w2r[c]));
            KAHAN_ADD(so[3], co[3], __fmul_rn(v, w3r[c]));
        }
    }
    const float o0 = __fadd_rn(__fsub_rn(so[0], co[0]), b3[a*4+0]);
    const float o1 = __fadd_rn(__fsub_rn(so[1], co[1]), b3[a*4+1]);
    const float o2 = __fadd_rn(__fsub_rn(so[2], co[2]), b3[a*4+2]);
    const float o3 = __fadd_rn(__fsub_rn(so[3], co[3]), b3[a*4+3]);

    const int ay = p / FW, ax = p % FW;
    const double cxd = (ax + 0.5) * 16.0;
    const double cyd = (ay + 0.5) * 16.0;
    const int si = a / 3, ri = a % 3;
    const double sz = (si == 0) ? 32.0 : (si == 1) ? 64.0 : 128.0;
    const double rr = (ri == 0) ? 0.5 : (ri == 1) ? 1.0 : 2.0;
    const float hf = (float)(sz * sqrt(rr));
    const float wf = (float)(sz / sqrt(rr));
    const float ax1 = (float)(cxd - (double)wf * 0.5);
    const float ay1 = (float)(cyd - (double)hf * 0.5);
    const float ax2 = (float)(cxd + (double)wf * 0.5);
    const float ay2 = (float)(cyd + (double)hf * 0.5);

    const float aw = __fsub_rn(ax2, ax1), ah = __fsub_rn(ay2, ay1);
    const float acx = __fadd_rn(ax1, __fmul_rn(0.5f, aw));
    const float acy = __fadd_rn(ay1, __fmul_rn(0.5f, ah));
    const float pcx = __fadd_rn(acx, __fmul_rn(o0, aw));
    const float pcy = __fadd_rn(acy, __fmul_rn(o1, ah));
    const float pw  = __fmul_rn(aw, (float)exp((double)o2));
    const float ph  = __fmul_rn(ah, (float)exp((double)o3));
    float x1 = __fsub_rn(pcx, __fmul_rn(0.5f, pw));
    float y1 = __fsub_rn(pcy, __fmul_rn(0.5f, ph));
    float x2 = __fadd_rn(pcx, __fmul_rn(0.5f, pw));
    float y2 = __fadd_rn(pcy, __fmul_rn(0.5f, ph));
    x1 = fminf(fmaxf(x1, 0.f), IMGW);
    y1 = fminf(fmaxf(y1, 0.f), IMGH);
    x2 = fminf(fmaxf(x2, 0.f), IMGW);
    y2 = fminf(fmaxf(y2, 0.f), IMGH);

    const float wb = x2 - x1, hb = y2 - y1;
    const bool valid = (wb >= 0.001f) && (hb >= 0.001f) && (s >= 0.5f);

    boxes[j] = make_float4(x1, y1, x2, y2);
    ss[j]    = s;
    __syncthreads();

    const float4 mb = boxes[j];
    const float myarea = (mb.z - mb.x) * (mb.w - mb.y);

    uint32_t msk[16];
#pragma unroll
    for (int c = 0; c < 16; c++) {
        uint32_t w = 0;
        for (int bit = 0; bit < 32; bit++) {
            int i = c*32 + bit;
            if (i < j) {
                float4 bi = boxes[i];
                float ltx = fmaxf(bi.x, mb.x), lty = fmaxf(bi.y, mb.y);
                float rbx = fminf(bi.z, mb.z), rby = fminf(bi.w, mb.w);
                float iw = fmaxf(rbx - ltx, 0.f), ih = fmaxf(rby - lty, 0.f);
                float inter = iw * ih;
                float ai = (bi.z - bi.x) * (bi.w - bi.y);
                float iou = inter / (ai + myarea - inter + 1e-9f);
                if (iou > 0.7f) w |= (1u << bit);
            }
        }
        msk[c] = w;
    }

    int mykeep = valid ? 1 : 0;
    for (int c = 0; c < 16; c++) {
        if (warp == c) {
            unsigned alive = __ballot_sync(0xffffffffu, mykeep);
            for (int bbit = 0; bbit < 32; bbit++) {
                unsigned sup = __ballot_sync(0xffffffffu,
                                             (msk[c] >> bbit) & 1u);
                if ((alive >> bbit) & 1u) alive &= ~sup;
            }
            mykeep = (alive >> lane) & 1u;
            if (lane == 0) aliveW[c] = alive;
        }
        __syncthreads();
        if (warp > c) {
            if (msk[c] & aliveW[c]) mykeep = 0;
        }
    }
    keep[j] = mykeep;
    __syncthreads();

    unsigned int m = __ballot_sync(0xffffffffu, keep[j] != 0);
    int pre = __popc(m & ((1u << lane) - 1u));
    if (lane == 0) warpcnt[warp] = __popc(m);
    __syncthreads();
    int base = 0, total = 0;
#pragma unroll
    for (int wi = 0; wi < 16; wi++) {
        int c = warpcnt[wi];
        if (wi < warp) base += c;
        total += c;
    }
    const int rank = base + pre;

    float* ob = out + (size_t)b * POST * 4;
    float* os = out + (size_t)BATCH * POST * 4 + (size_t)b * POST;

    if (j < POST && j >= total) {
        ob[j*4+0] = 0.f; ob[j*4+1] = 0.f; ob[j*4+2] = 0.f; ob[j*4+3] = 0.f;
        os[j] = 0.f;
    }
    if (keep[j] && rank < POST) {
        ob[rank*4+0] = mb.x; ob[rank*4+1] = mb.y;
        ob[rank*4+2] = mb.z; ob[rank*4+3] = mb.w;
        os[rank] = ss[j];
    }
}

extern "C" void kernel_launch(void* const* d_in, const int* in_sizes, int n_in,
                              void* d_out, int out_size)
{
    const float* fm = (const float*)d_in[0];
    const float* w1 = (const float*)d_in[1];
    const float* b1 = (const float*)d_in[2];
    const float* w2 = (const float*)d_in[3];
    const float* b2 = (const float*)d_in[4];
    const float* w3 = (const float*)d_in[5];
    const float* b3 = (const float*)d_in[6];
    float* out = (float*)d_out;

    zero_pads_kernel<<<1024, 256>>>();
    prep_x_kernel<<<dim3(79, 16, BATCH), 256>>>(fm);
    prep_w_kernel<<<864, 256>>>(w1);

    const int conv_smem = 3*BUF2 + 16;   // 184336 B
    cudaFuncSetAttribute(conv_mma_kernel,
                         cudaFuncAttributeMaxDynamicSharedMemorySize, conv_smem);
    conv_mma_kernel<<<dim3(NPXT, CIN/OCB, BATCH), 256, conv_smem>>>(b1);

    cls_kernel<<<dim3((HW + 255) / 256, BATCH), 256>>>(w2, b2);

    const int topk_smem = 32768*4 + 1024*4 + 1024*8;
    cudaFuncSetAttribute(topk_kernel,
                         cudaFuncAttributeMaxDynamicSharedMemorySize, topk_smem);
    topk_kernel<<<BATCH, 1024, topk_smem>>>();

    const int prop_smem = W3S_FLOATS*4 + PRE*16 + PRE*4 + PRE*4;
    cudaFuncSetAttribute(proposal_kernel,
                         cudaFuncAttributeMaxDynamicSharedMemorySize, prop_smem);
    proposal_kernel<<<BATCH, PRE, prop_smem>>>(w3, b3, out);
}

// round 17
// speedup vs baseline: 1.1483x; 1.1483x over previous
#include <cuda_runtime.h>
#include <cuda_bf16.h>
#include <math.h>
#include <stdint.h>

#define BATCH 16
#define CIN   512
#define FH    50
#define FW    50
#define HW    2500
#define NANCH 9
#define NTOT  (HW*NANCH)
#define PRE   512
#define POST  128
#define IMGW  800.0f
#define IMGH  800.0f
#define OCB   128
#define PXB   128
#define NPXT  20
#define XROWS 2688
#define XPAD  64
#define RS    72
#define TILE_B (128*RS*2)
#define BUF_B (6*TILE_B)

#define KAHAN_ADD(s, c, p) do {                        \
    float _y = __fsub_rn((p), (c));                    \
    float _t = __fadd_rn((s), _y);                     \
    (c) = __fsub_rn(__fsub_rn(_t, (s)), _y);           \
    (s) = _t;                                          \
} while (0)

__device__ float g_shared[(size_t)BATCH*CIN*HW];
__device__ float g_scores[(size_t)BATCH*NTOT];
__device__ int   g_topidx[BATCH*PRE];
__device__ float g_topscore[BATCH*PRE];
__device__ float g_offs[BATCH*PRE*4];
__device__ __align__(16) __nv_bfloat16 g_xsT[9][BATCH][XROWS][CIN];
__device__ __align__(16) __nv_bfloat16 g_wA[(size_t)864*8192];

__device__ __forceinline__ uint32_t smem_u32(const void* p) {
    uint32_t a;
    asm("{ .reg .u64 t; cvta.to.shared.u64 t, %1; cvt.u32.u64 %0, t; }"
        : "=r"(a) : "l"(p));
    return a;
}
__device__ __forceinline__ void split3(float v, __nv_bfloat16& s0,
                                       __nv_bfloat16& s1, __nv_bfloat16& s2) {
    s0 = __float2bfloat16_rn(v);
    float r1 = __fsub_rn(v, __bfloat162float(s0));
    s1 = __float2bfloat16_rn(r1);
    float r2 = __fsub_rn(r1, __bfloat162float(s1));
    s2 = __float2bfloat16_rn(r2);
}

__global__ __launch_bounds__(256) void zero_pads_kernel() {
    const int nrows = XPAD + (XROWS - XPAD - HW);
    size_t total = (size_t)9 * BATCH * nrows * CIN / 8;
    uint4 z = make_uint4(0,0,0,0);
    for (size_t i = blockIdx.x * 256ull + threadIdx.x; i < total;
         i += (size_t)gridDim.x * 256ull) {
        size_t e = i * 8;
        int ic  = e % CIN;
        size_t r = e / CIN;
        int row = r % nrows;
        size_t jb = r / nrows;
        int b = jb % BATCH;
        int j = jb / BATCH;
        int xrow = (row < XPAD) ? row : (row - XPAD + XPAD + HW);
        *(uint4*)&g_xsT[j][b][xrow][ic] = z;
    }
}

__global__ __launch_bounds__(256) void prep_x_kernel(const float* __restrict__ x) {
    __shared__ float Xt[32][34];
    const int p0x = blockIdx.x * 32;
    const int i0  = blockIdx.y * 32;
    const int b   = blockIdx.z;
    const int tid = threadIdx.x;
    for (int e = tid; e < 32*34; e += 256) {
        int ic = e / 34, c = e % 34;
        int p = p0x - 1 + c;
        Xt[ic][c] = (p >= 0 && p < HW)
            ? x[((size_t)b*CIN + i0 + ic)*HW + p] : 0.f;
    }
    __syncthreads();
    for (int e = tid; e < 32*32; e += 256) {
        int pl = e >> 5, ic = e & 31;
        int p = p0x + pl;
        if (p >= HW) continue;
        int xcol = p % FW;
#pragma unroll
        for (int dxi = 0; dxi < 3; dxi++) {
            int xc = xcol + dxi - 1;
            float v = (xc >= 0 && xc < FW) ? Xt[ic][pl + dxi] : 0.f;
            __nv_bfloat16 s0, s1, s2;
            split3(v, s0, s1, s2);
            g_xsT[0*3 + dxi][b][p + XPAD][i0 + ic] = s0;
            g_xsT[1*3 + dxi][b][p + XPAD][i0 + ic] = s1;
            g_xsT[2*3 + dxi][b][p + XPAD][i0 + ic] = s2;
        }
    }
}

__global__ __launch_bounds__(256) void prep_w_kernel(const float* __restrict__ w1) {
    const int id = blockIdx.x;
    const int ocblk = id & 3;
    const int icblk = (id >> 2) & 7;
    const int tmp = id >> 5;
    const int t = tmp % 9;
    const int j = tmp / 9;
    __nv_bfloat16* dst = g_wA + (size_t)id * 8192;
    for (int e = threadIdx.x; e < 8192; e += 256) {
        int r = e >> 6, c = e & 63;
        int oc = ocblk*128 + r;
        int ic = icblk*64 + c;
        float w = w1[(size_t)oc*(CIN*9) + ic*9 + t];
        __nv_bfloat16 s0, s1, s2;
        split3(w, s0, s1, s2);
        dst[r*64 + c] = (j == 0) ? s0 : (j == 1) ? s1 : s2;
    }
}

__device__ __forceinline__ void stage_chunk_async(
    uint32_t buf, int ch, int ocblk, int b, int p0, int tid)
{
    const int t = ch / 8, icblk = ch % 8;
    const int dy = t / 3 - 1, dxi = t % 3;
    for (int e = tid; e < 3072; e += 256) {
        int j = e >> 10, r = (e >> 3) & 127, c8 = e & 7;
        const __nv_bfloat16* src = g_wA +
            (size_t)(((j*9 + t)*8 + icblk)*4 + ocblk) * 8192 + r*64 + c8*8;
        uint32_t d = buf + (uint32_t)(j*TILE_B + r*(RS*2) + c8*16);
        asm volatile("cp.async.cg.shared.global [%0], [%1], 16;"
                     :: "r"(d), "l"(src));
    }
    const int rowbase = p0 + dy*FW + XPAD;
    for (int e = tid; e < 3072; e += 256) {
        int j = e >> 10, r = (e >> 3) & 127, c8 = e & 7;
        const __nv_bfloat16* src =
            &g_xsT[j*3 + dxi][b][rowbase + r][icblk*64] + c8*8;
        uint32_t d = buf + (uint32_t)(3*TILE_B + j*TILE_B + r*(RS*2) + c8*16);
        asm volatile("cp.async.cg.shared.global [%0], [%1], 16;"
                     :: "r"(d), "l"(src));
    }
    asm volatile("cp.async.commit_group;");
}

__global__ __launch_bounds__(256, 1)
void conv_mma_kernel(const float* __restrict__ b1) {
    extern __shared__ unsigned char dsm[];
    const uint32_t sb0 = (smem_u32(dsm) + 15u) & ~15u;

    const int tid  = threadIdx.x;
    const int wid  = tid >> 5;
    const int lane = tid & 31;
    const int pxblk = blockIdx.x, ocblk = blockIdx.y, b = blockIdx.z;
    const int p0 = pxblk * PXB;
    const int warp_m0 = (wid & 1) * 64;
    const int warp_n0 = (wid >> 1) * 32;

    float accL[4][4][4], accS[4][4][4];
#pragma unroll
    for (int mt = 0; mt < 4; mt++)
#pragma unroll
        for (int nt = 0; nt < 4; nt++)
#pragma unroll
            for (int r = 0; r < 4; r++) { accL[mt][nt][r] = 0.f; accS[mt][nt][r] = 0.f; }

    stage_chunk_async(sb0, 0, ocblk, b, p0, tid);

    for (int ch = 0; ch < 72; ch++) {
        const uint32_t cur = sb0 + (uint32_t)((ch & 1) * BUF_B);
        const uint32_t nxt = sb0 + (uint32_t)(((ch + 1) & 1) * BUF_B);

        asm volatile("cp.async.wait_group 0;" ::: "memory");
        __syncthreads();

        if (ch + 1 < 72)
            stage_chunk_async(nxt, ch + 1, ocblk, b, p0, tid);

        const uint32_t sbA = cur;
        const uint32_t sbB = cur + 3*TILE_B;

#pragma unroll
        for (int ks = 0; ks < 4; ks++) {
            const int k0 = ks * 16;
            uint32_t bf[3][4][2];
#pragma unroll
            for (int s = 0; s < 3; s++)
#pragma unroll
                for (int nt = 0; nt < 4; nt++) {
                    int row = warp_n0 + nt*8 + (lane & 7);
                    int colb = (k0 + ((lane >> 3) & 1)*8) * 2;
                    uint32_t a = sbB + s*TILE_B + row*(RS*2) + colb;
                    asm volatile(
                        "ldmatrix.sync.aligned.m8n8.x2.shared.b16 {%0,%1}, [%2];"
                        : "=r"(bf[s][nt][0]), "=r"(bf[s][nt][1]) : "r"(a));
                }
#pragma unroll
            for (int j = 0; j < 3; j++) {
                uint32_t af[4][4];
#pragma unroll
                for (int mt = 0; mt < 4; mt++) {
                    int row = warp_m0 + mt*16 + (lane & 15);
                    int colb = (k0 + (lane >> 4)*8) * 2;
                    uint32_t a = sbA + j*TILE_B + row*(RS*2) + colb;
                    asm volatile(
                        "ldmatrix.sync.aligned.m8n8.x4.shared.b16 {%0,%1,%2,%3}, [%4];"
                        : "=r"(af[mt][0]), "=r"(af[mt][1]),
                          "=r"(af[mt][2]), "=r"(af[mt][3]) : "r"(a));
                }
                const int nk = (j == 0) ? 3 : (j == 1) ? 2 : 1;
#pragma unroll
                for (int k = 0; k < 3; k++) {
                    if (k >= nk) break;
#pragma unroll
                    for (int mt = 0; mt < 4; mt++)
#pragma unroll
                        for (int nt = 0; nt < 4; nt++) {
                            asm volatile(
                                "mma.sync.aligned.m16n8k16.row.col.f32.bf16.bf16.f32 "
                                "{%0,%1,%2,%3}, {%4,%5,%6,%7}, {%8,%9}, {%0,%1,%2,%3};"
                                : "+f"(accS[mt][nt][0]), "+f"(accS[mt][nt][1]),
                                  "+f"(accS[mt][nt][2]), "+f"(accS[mt][nt][3])
                                : "r"(af[mt][0]), "r"(af[mt][1]),
                                  "r"(af[mt][2]), "r"(af[mt][3]),
                                  "r"(bf[k][nt][0]), "r"(bf[k][nt][1]));
                        }
                }
            }
        }
        if ((ch & 3) == 3) {
#pragma unroll
            for (int mt = 0; mt < 4; mt++)
#pragma unroll
                for (int nt = 0; nt < 4; nt++)
#pragma unroll
                    for (int r = 0; r < 4; r++) {
                        accL[mt][nt][r] = __fadd_rn(accL[mt][nt][r],
                                                    accS[mt][nt][r]);
                        accS[mt][nt][r] = 0.f;
                    }
        }
    }

#pragma unroll
    for (int mt = 0; mt < 4; mt++) {
#pragma unroll
        for (int half = 0; half < 2; half++) {
            int oc = ocblk*128 + warp_m0 + mt*16 + (lane >> 2) + half*8;
            float bias = b1[oc];
            float* op = g_shared + ((size_t)b*CIN + oc)*HW;
#pragma unroll
            for (int nt = 0; nt < 4; nt++) {
#pragma unroll
                for (int e = 0; e < 2; e++) {
                    int px = p0 + warp_n0 + nt*8 + (lane & 3)*2 + e;
                    if (px < HW) {
                        float v = __fadd_rn(accL[mt][nt][half*2 + e], bias);
                        op[px] = fmaxf(v, 0.f);
                    }
                }
            }
        }
    }
}

__global__ __launch_bounds__(256) void cls_kernel(
    const float* __restrict__ w2, const float* __restrict__ b2)
{
    __shared__ float w2s[9][512];
    const int b = blockIdx.y;
    const int p = blockIdx.x * 256 + threadIdx.x;
    for (int i = threadIdx.x; i < 9*512; i += 256)
        w2s[i/512][i%512] = w2[i];
    __syncthreads();
    if (p >= HW) return;
    float acc[9], cmp[9];
#pragma unroll
    for (int a = 0; a < 9; a++) { acc[a] = 0.f; cmp[a] = 0.f; }
    const float* sp = g_shared + (size_t)b * CIN * HW + p;
    for (int c = 0; c < CIN; c++) {
        float v = sp[(size_t)c * HW];
#pragma unroll
        for (int a = 0; a < 9; a++)
            KAHAN_ADD(acc[a], cmp[a], __fmul_rn(v, w2s[a][c]));
    }
    float* outp = g_scores + (size_t)b * NTOT + (size_t)p * 9;
#pragma unroll
    for (int a = 0; a < 9; a++) {
        float logit = __fadd_rn(__fsub_rn(acc[a], cmp[a]), b2[a]);
        double sg = 1.0 / (1.0 + exp(-(double)logit));
        outp[a] = (float)sg;
    }
}

__global__ __launch_bounds__(1024) void topk_kernel()
{
    extern __shared__ unsigned char smraw[];
    unsigned int* hist = (unsigned int*)smraw;
    unsigned int* csum = hist + 32768;
    unsigned long long* cand = (unsigned long long*)(csum + 1024);
    __shared__ int s_tb, s_cntgt, s_thr, s_cnt;
    const int b = blockIdx.x, tid = threadIdx.x;
    const float* sc = g_scores + (size_t)b * NTOT;

    for (int i = tid; i < 32768; i += 1024) hist[i] = 0;
    __syncthreads();
    for (int i = tid; i < NTOT; i += 1024)
        atomicAdd(&hist[__float_as_uint(sc[i]) >> 15], 1u);
    __syncthreads();
    { unsigned int cs = 0;
#pragma unroll 4
      for (int k = 0; k < 32; k++) cs += hist[tid*32 + k];
      csum[tid] = cs; }
    __syncthreads();
    if (tid == 0) {
        unsigned int accum = 0;
        int ch = 1023;
        for (; ch > 0; ch--) { if (accum + csum[ch] >= PRE) break; accum += csum[ch]; }
        int bk = ch*32 + 31;
        for (; bk > ch*32; bk--) { if (accum + hist[bk] >= PRE) break; accum += hist[bk]; }
        s_tb = bk; s_cntgt = (int)accum;
    }
    __syncthreads();
    const int tb = s_tb, cntgt = s_cntgt;

    for (int i = tid; i < 32768; i += 1024) hist[i] = 0;
    __syncthreads();
    for (int i = tid; i < NTOT; i += 1024) {
        unsigned int bits = __float_as_uint(sc[i]);
        if ((int)(bits >> 15) == tb) atomicAdd(&hist[bits & 0x7FFF], 1u);
    }
    __syncthreads();
    { unsigned int cs = 0;
#pragma unroll 4
      for (int k = 0; k < 32; k++) cs += hist[tid*32 + k];
      csum[tid] = cs; }
    __syncthreads();
    if (tid == 0) {
        unsigned int accum = (unsigned int)cntgt;
        int ch = 1023;
        for (; ch > 0; ch--) { if (accum + csum[ch] >= PRE) break; accum += csum[ch]; }
        int bk = ch*32 + 31;
        for (; bk > ch*32; bk--) { if (accum + hist[bk] >= PRE) break; accum += hist[bk]; }
        s_thr = (tb << 15) | bk;
        s_cnt = 0;
    }
    __syncthreads();
    const unsigned int thrbits = (unsigned int)s_thr;

    for (int i = tid; i < NTOT; i += 1024) {
        unsigned int bits = __float_as_uint(sc[i]);
        if (bits >= thrbits) {
            int pos = atomicAdd(&s_cnt, 1);
            if (pos < 1024)
                cand[pos] = ((unsigned long long)bits << 32) |
                            (unsigned long long)(0xFFFFFFFFu - (unsigned int)i);
        }
    }
    __syncthreads();
    int cnt = s_cnt; if (cnt > 1024) cnt = 1024;
    if (tid >= cnt) cand[tid] = 0ULL;
    __syncthreads();

    for (int k = 2; k <= 1024; k <<= 1) {
        for (int j = k >> 1; j > 0; j >>= 1) {
            int ixj = tid ^ j;
            if (ixj > tid) {
                unsigned long long a = cand[tid], c = cand[ixj];
                bool up = ((tid & k) == 0);
                if (up ? (a < c) : (a > c)) { cand[tid] = c; cand[ixj] = a; }
            }
            __syncthreads();
        }
    }
    if (tid < PRE) {
        unsigned long long key = cand[tid];
        unsigned int idx = 0xFFFFFFFFu - (unsigned int)(key & 0xFFFFFFFFull);
        g_topidx[b*PRE + tid]   = (int)idx;
        g_topscore[b*PRE + tid] = __uint_as_float((unsigned int)(key >> 32));
    }
}

// ==== K4a: offsets for all candidates, chip-wide (bit-identical Kahan) ===
__global__ __launch_bounds__(256) void offsets_kernel(
    const float* __restrict__ w3, const float* __restrict__ b3)
{
    const int b = blockIdx.y;
    const int gt = blockIdx.x * 256 + threadIdx.x;   // 2048 per image
    const int j = gt >> 2, q = gt & 3;
    if (j >= PRE) return;

    const int idx = g_topidx[b*PRE + j];
    const int p = idx / 9, a = idx % 9;

    float s = 0.f, c0 = 0.f;
    const float* col = g_shared + (size_t)b * CIN * HW + p;
    const float* wr  = w3 + (size_t)(a*4 + q) * CIN;
    for (int c = 0; c < CIN; c++) {
        float v = col[(size_t)c * HW];
        KAHAN_ADD(s, c0, __fmul_rn(v, __ldg(&wr[c])));
    }
    g_offs[(b*PRE + j)*4 + q] =
        __fadd_rn(__fsub_rn(s, c0), b3[a*4 + q]);
}

// ====== K4b: decode + clip + NMS + output (grid 16) ======================
__global__ __launch_bounds__(512) void proposal_kernel(float* __restrict__ out)
{
    __shared__ float4 boxes[PRE];
    __shared__ float  ss[PRE];
    __shared__ int    keep[PRE];
    __shared__ uint32_t aliveW[16];
    __shared__ int warpcnt[16];
    const int b = blockIdx.x;
    const int j = threadIdx.x;
    const int lane = j & 31, warp = j >> 5;

    const int   idx = g_topidx[b*PRE + j];
    const float s   = g_topscore[b*PRE + j];
    const int p = idx / 9, a = idx % 9;

    const float o0 = g_offs[(b*PRE + j)*4 + 0];
    const float o1 = g_offs[(b*PRE + j)*4 + 1];
    const float o2 = g_offs[(b*PRE + j)*4 + 2];
    const float o3 = g_offs[(b*PRE + j)*4 + 3];

    const int ay = p / FW, ax = p % FW;
    const double cxd = (ax + 0.5) * 16.0;
    const double cyd = (ay + 0.5) * 16.0;
    const int si = a / 3, ri = a % 3;
    const double sz = (si == 0) ? 32.0 : (si == 1) ? 64.0 : 128.0;
    const double rr = (ri == 0) ? 0.5 : (ri == 1) ? 1.0 : 2.0;
    const float hf = (float)(sz * sqrt(rr));
    const float wf = (float)(sz / sqrt(rr));
    const float ax1 = (float)(cxd - (double)wf * 0.5);
    const float ay1 = (float)(cyd - (double)hf * 0.5);
    const float ax2 = (float)(cxd + (double)wf * 0.5);
    const float ay2 = (float)(cyd + (double)hf * 0.5);

    const float aw = __fsub_rn(ax2, ax1), ah = __fsub_rn(ay2, ay1);
    const float acx = __fadd_rn(ax1, __fmul_rn(0.5f, aw));
    const float acy = __fadd_rn(ay1, __fmul_rn(0.5f, ah));
    const float pcx = __fadd_rn(acx, __fmul_rn(o0, aw));
    const float pcy = __fadd_rn(acy, __fmul_rn(o1, ah));
    const float pw  = __fmul_rn(aw, (float)exp((double)o2));
    const float ph  = __fmul_rn(ah, (float)exp((double)o3));
    float x1 = __fsub_rn(pcx, __fmul_rn(0.5f, pw));
    float y1 = __fsub_rn(pcy, __fmul_rn(0.5f, ph));
    float x2 = __fadd_rn(pcx, __fmul_rn(0.5f, pw));
    float y2 = __fadd_rn(pcy, __fmul_rn(0.5f, ph));
    x1 = fminf(fmaxf(x1, 0.f), IMGW);
    y1 = fminf(fmaxf(y1, 0.f), IMGH);
    x2 = fminf(fmaxf(x2, 0.f), IMGW);
    y2 = fminf(fmaxf(y2, 0.f), IMGH);

    const float wb = x2 - x1, hb = y2 - y1;
    const bool valid = (wb >= 0.001f) && (hb >= 0.001f) && (s >= 0.5f);

    boxes[j] = make_float4(x1, y1, x2, y2);
    ss[j]    = s;
    __syncthreads();

    const float4 mb = boxes[j];
    const float myarea = (mb.z - mb.x) * (mb.w - mb.y);

    uint32_t msk[16];
#pragma unroll
    for (int c = 0; c < 16; c++) {
        uint32_t w = 0;
        for (int bit = 0; bit < 32; bit++) {
            int i = c*32 + bit;
            if (i < j) {
                float4 bi = boxes[i];
                float ltx = fmaxf(bi.x, mb.x), lty = fmaxf(bi.y, mb.y);
                float rbx = fminf(bi.z, mb.z), rby = fminf(bi.w, mb.w);
                float iw = fmaxf(rbx - ltx, 0.f), ih = fmaxf(rby - lty, 0.f);
                float inter = iw * ih;
                float ai = (bi.z - bi.x) * (bi.w - bi.y);
                float iou = inter / (ai + myarea - inter + 1e-9f);
                if (iou > 0.7f) w |= (1u << bit);
            }
        }
        msk[c] = w;
    }

    int mykeep = valid ? 1 : 0;
    for (int c = 0; c < 16; c++) {
        if (warp == c) {
            unsigned alive = __ballot_sync(0xffffffffu, mykeep);
            for (int bbit = 0; bbit < 32; bbit++) {
                unsigned sup = __ballot_sync(0xffffffffu,
                                             (msk[c] >> bbit) & 1u);
                if ((alive >> bbit) & 1u) alive &= ~sup;
            }
            mykeep = (alive >> lane) & 1u;
            if (lane == 0) aliveW[c] = alive;
        }
        __syncthreads();
        if (warp > c) {
            if (msk[c] & aliveW[c]) mykeep = 0;
        }
    }
    keep[j] = mykeep;
    __syncthreads();

    unsigned int m = __ballot_sync(0xffffffffu, keep[j] != 0);
    int pre = __popc(m & ((1u << lane) - 1u));
    if (lane == 0) warpcnt[warp] = __popc(m);
    __syncthreads();
    int base = 0, total = 0;
#pragma unroll
    for (int wi = 0; wi < 16; wi++) {
        int c = warpcnt[wi];
        if (wi < warp) base += c;
        total += c;
    }
    const int rank = base + pre;

    float* ob = out + (size_t)b * POST * 4;
    float* os = out + (size_t)BATCH * POST * 4 + (size_t)b * POST;

    if (j < POST && j >= total) {
        ob[j*4+0] = 0.f; ob[j*4+1] = 0.f; ob[j*4+2] = 0.f; ob[j*4+3] = 0.f;
        os[j] = 0.f;
    }
    if (keep[j] && rank < POST) {
        ob[rank*4+0] = mb.x; ob[rank*4+1] = mb.y;
        ob[rank*4+2] = mb.z; ob[rank*4+3] = mb.w;
        os[rank] = ss[j];
    }
}

extern "C" void kernel_launch(void* const* d_in, const int* in_sizes, int n_in,
                              void* d_out, int out_size)
{
    const float* fm = (const float*)d_in[0];
    const float* w1 = (const float*)d_in[1];
    const float* b1 = (const float*)d_in[2];
    const float* w2 = (const float*)d_in[3];
    const float* b2 = (const float*)d_in[4];
    const float* w3 = (const float*)d_in[5];
    const float* b3 = (const float*)d_in[6];
    float* out = (float*)d_out;

    zero_pads_kernel<<<1024, 256>>>();
    prep_x_kernel<<<dim3(79, 16, BATCH), 256>>>(fm);
    prep_w_kernel<<<864, 256>>>(w1);

    const int conv_smem = 2*BUF_B + 16;
    cudaFuncSetAttribute(conv_mma_kernel,
                         cudaFuncAttributeMaxDynamicSharedMemorySize, conv_smem);
    conv_mma_kernel<<<dim3(NPXT, CIN/OCB, BATCH), 256, conv_smem>>>(b1);

    cls_kernel<<<dim3((HW + 255) / 256, BATCH), 256>>>(w2, b2);

    const int topk_smem = 32768*4 + 1024*4 + 1024*8;
    cudaFuncSetAttribute(topk_kernel,
                         cudaFuncAttributeMaxDynamicSharedMemorySize, topk_smem);
    topk_kernel<<<BATCH, 1024, topk_smem>>>();

    offsets_kernel<<<dim3(8, BATCH), 256>>>(w3, b3);
    proposal_kernel<<<BATCH, PRE>>>(out);
}